// round 1
// baseline (speedup 1.0000x reference)
#include <cuda_runtime.h>
#include <math.h>

// RealNVP backward_xz + log-density sum.
// Inputs (metadata order): x(131072,2) f32, W1(32,1,64), b1(32,64), W2(32,64,64),
// b2(32,64), W3(32,64,2), b3(32,2), loc(2), log_scale(2). Output: scalar f32.

#define N_SAMPLES 131072
#define NBLOCKS   32
#define HDIM      64
#define LIMIT_R   10.0f
#define CLAMPV    10000.0f
#define NCTA      512
#define TPB       256

__device__ float g_partials[NCTA];

__global__ __launch_bounds__(TPB) void realnvp_main(
    const float* __restrict__ x,
    const float* __restrict__ W1, const float* __restrict__ b1,
    const float* __restrict__ W2, const float* __restrict__ b2,
    const float* __restrict__ W3, const float* __restrict__ b3,
    const float* __restrict__ loc, const float* __restrict__ logs)
{
    __shared__ float sW2[HDIM * HDIM];   // natural [i][j] layout, rows 256B (float4-aligned)
    __shared__ float sW1[HDIM], sb1[HDIM], sb2[HDIM];
    __shared__ float sW3[2 * HDIM], sb3[2];
    __shared__ float sred[TPB];

    const int tid = threadIdx.x;
    const int n   = blockIdx.x * TPB + tid;

    float z0 = x[2 * n + 0];
    float z1 = x[2 * n + 1];
    float ld = 0.0f;
    bool  mask = true;

    const float loc0 = loc[0],  loc1 = loc[1];
    const float ls0  = logs[0], ls1  = logs[1];

    for (int s = 0; s < NBLOCKS; s++) {
        const int blk = NBLOCKS - 1 - s;   // scan runs params reversed

        __syncthreads();   // previous iteration's readers done before overwrite

        // ---- stage this block's weights into SMEM (coalesced float4) ----
        {
            const float4* W2v = (const float4*)(W2 + blk * HDIM * HDIM);
            float4* sW2v = (float4*)sW2;
            #pragma unroll
            for (int k = 0; k < 4; k++)
                sW2v[tid + k * TPB] = W2v[tid + k * TPB];

            if (tid < HDIM) {
                sW1[tid] = W1[blk * HDIM + tid];
                sb1[tid] = b1[blk * HDIM + tid];
                sb2[tid] = b2[blk * HDIM + tid];
            } else if (tid < HDIM + 2 * HDIM) {
                sW3[tid - HDIM] = W3[blk * 2 * HDIM + (tid - HDIM)];
            } else if (tid < HDIM + 2 * HDIM + 2) {
                sb3[tid - HDIM - 2 * HDIM] = b3[blk * 2 + (tid - HDIM - 2 * HDIM)];
            }
        }
        __syncthreads();

        // ---- mask update + swap (clip is a no-op when mask holds: |z| < 10) ----
        bool inr = (fabsf(z0) < LIMIT_R) && (fabsf(z1) < LIMIT_R);
        mask = mask && inr;
        if (mask) { float t = z0; z0 = z1; z1 = t; }
        // NOTE: the reference's second mask check is redundant: if mask holds
        // here, the swapped z still has |z| < 10, so it re-passes.

        // ---- MLP: h1 = relu(z0*w1+b1); h2 = relu(h1@W2+b2); param = h2@W3+b3 ----
        float acc[HDIM];
        #pragma unroll
        for (int j = 0; j < HDIM; j++) acc[j] = sb2[j];

        #pragma unroll 4
        for (int i = 0; i < HDIM; i++) {
            float hi = fmaxf(fmaf(z0, sW1[i], sb1[i]), 0.0f);
            const float4* row = (const float4*)(sW2 + i * HDIM);
            #pragma unroll
            for (int j4 = 0; j4 < HDIM / 4; j4++) {
                float4 w = row[j4];
                acc[4 * j4 + 0] = fmaf(hi, w.x, acc[4 * j4 + 0]);
                acc[4 * j4 + 1] = fmaf(hi, w.y, acc[4 * j4 + 1]);
                acc[4 * j4 + 2] = fmaf(hi, w.z, acc[4 * j4 + 2]);
                acc[4 * j4 + 3] = fmaf(hi, w.w, acc[4 * j4 + 3]);
            }
        }

        float p0 = sb3[0], p1 = sb3[1];
        #pragma unroll
        for (int j = 0; j < HDIM; j++) {
            float h2 = fmaxf(acc[j], 0.0f);
            p0 = fmaf(h2, sW3[2 * j + 0], p0);   // shift
            p1 = fmaf(h2, sW3[2 * j + 1], p1);   // scale
        }

        float z1n = (z1 - p0) * expf(-p1);
        z1n = fminf(fmaxf(z1n, -CLAMPV), CLAMPV);
        if (mask) { z1 = z1n; ld -= p1; }
        // z0 (passive coord) already |z0|<10 under mask, clip is a no-op
    }

    // ---- base log-density + accumulated log-det ----
    float t0 = (z0 - loc0) * expf(-ls0);
    float t1 = (z1 - loc1) * expf(-ls1);
    float val = -1.8378770664093454836f            // -0.5*D*log(2*pi), D=2
                - (ls0 + ls1)
                - 0.5f * (t0 * t0 + t1 * t1)
                + ld;

    // ---- deterministic CTA tree reduction ----
    sred[tid] = val;
    __syncthreads();
    #pragma unroll
    for (int off = TPB / 2; off > 0; off >>= 1) {
        if (tid < off) sred[tid] += sred[tid + off];
        __syncthreads();
    }
    if (tid == 0) g_partials[blockIdx.x] = sred[0];
}

__global__ __launch_bounds__(NCTA) void realnvp_reduce(float* __restrict__ out)
{
    __shared__ double sr[NCTA];
    const int t = threadIdx.x;
    sr[t] = (double)g_partials[t];
    __syncthreads();
    #pragma unroll
    for (int off = NCTA / 2; off > 0; off >>= 1) {
        if (t < off) sr[t] += sr[t + off];
        __syncthreads();
    }
    if (t == 0) out[0] = (float)sr[0];
}

extern "C" void kernel_launch(void* const* d_in, const int* in_sizes, int n_in,
                              void* d_out, int out_size)
{
    const float* x    = (const float*)d_in[0];
    const float* W1   = (const float*)d_in[1];
    const float* b1   = (const float*)d_in[2];
    const float* W2   = (const float*)d_in[3];
    const float* b2   = (const float*)d_in[4];
    const float* W3   = (const float*)d_in[5];
    const float* b3   = (const float*)d_in[6];
    const float* loc  = (const float*)d_in[7];
    const float* logs = (const float*)d_in[8];

    realnvp_main<<<NCTA, TPB>>>(x, W1, b1, W2, b2, W3, b3, loc, logs);
    realnvp_reduce<<<1, NCTA>>>((float*)d_out);
}